// round 16
// baseline (speedup 1.0000x reference)
#include <cuda_runtime.h>
#include <cuda_fp16.h>
#include <stdint.h>
#include <math.h>

#define N_NODES 30000
#define N_GENES 2000
#define HDIM    128
#define ZDIM    20
#define SDIM    10
#define N_EDGES 960000
#define VAR_EPS 1e-4f

// ---------------- scratch (static device globals; no allocations) ------------
__device__ __align__(16) float g_h0[N_NODES * HDIM];
__device__ __align__(16) float g_h1[N_NODES * HDIM];
__device__ __align__(16) float g_qmv[N_NODES * 40];
__device__ __align__(16) __half g_xlh[N_NODES * 24];   // [m(10)|v(10)|pad(4)]
__device__ __align__(16) __half g_xrh[N_NODES * 24];
__device__ __align__(16) float g_num[N_NODES * 20];
__device__ __align__(8)  float2 g_sum2[N_NODES];
__device__ __align__(16) float g_zall[N_NODES * 30];
__device__ __align__(16) float g_hd[N_NODES * HDIM];
__device__ float g_rowsum[N_NODES];

// fp16 weight buffers, transposed to [N][K]
__device__ __align__(16) __half g_bt0[HDIM * N_GENES];
__device__ __align__(16) __half g_bt1[HDIM * HDIM];
__device__ __align__(16) __half g_bth[40 * HDIM];
__device__ __align__(16) __half g_btd[N_GENES * HDIM];
__device__ float g_biash[40];

// ---------------- vector reductions (sm_90+) ----------------------------------
__device__ __forceinline__ void red_v2(float2* p, float a, float b) {
    asm volatile("red.global.add.v2.f32 [%0], {%1,%2};"
                 :: "l"(p), "f"(a), "f"(b) : "memory");
}
__device__ __forceinline__ void red_v4(float* p, float a, float b, float c, float d) {
    asm volatile("red.global.add.v4.f32 [%0], {%1,%2,%3,%4};"
                 :: "l"(p), "f"(a), "f"(b), "f"(c), "f"(d) : "memory");
}

// ---------------- fp16 helpers ------------------------------------------------
__device__ __forceinline__ uint32_t pack_h2(float a, float b) {
    uint32_t r;
    asm("cvt.rn.f16x2.f32 %0, %2, %1;" : "=r"(r) : "f"(a), "f"(b));
    return r;
}
// unpack 20 floats from a 24-half padded row (aligned vector loads)
__device__ __forceinline__ void ld20h(const __half* p, float x[20]) {
    const uint4* q = (const uint4*)p;
    uint4 a = q[0], b = q[1];
    uint32_t w[10];
    w[0] = a.x; w[1] = a.y; w[2] = a.z; w[3] = a.w;
    w[4] = b.x; w[5] = b.y; w[6] = b.z; w[7] = b.w;
    uint2 c = *(const uint2*)(p + 16);
    w[8] = c.x; w[9] = c.y;
    #pragma unroll
    for (int i = 0; i < 10; i++) {
        float2 f = __half22float2(*(__half2*)&w[i]);
        x[2 * i] = f.x; x[2 * i + 1] = f.y;
    }
}

// ---------------- weight transpose: B[K][N] -> T[N][K] fp16 ------------------
__global__ void transpose_split(const float* __restrict__ B,
                                __half* __restrict__ Th,
                                int K, int N) {
    __shared__ float tile[32][33];
    int kb = blockIdx.y * 32, nb = blockIdx.x * 32;
    for (int i = threadIdx.y; i < 32; i += 8) {
        int k = kb + i, n = nb + threadIdx.x;
        tile[i][threadIdx.x] = (k < K && n < N) ? B[(size_t)k * N + n] : 0.f;
    }
    __syncthreads();
    for (int i = threadIdx.y; i < 32; i += 8) {
        int n = nb + i, k = kb + threadIdx.x;
        if (n < N && k < K)
            Th[(size_t)n * K + k] = __float2half_rn(tile[threadIdx.x][i]);
    }
}

// concat [Wm | Wv] (each HDIM x ZDIM) into head weight T[40][128] + bias[40]
__global__ void prep_heads(const float* __restrict__ Wm, const float* __restrict__ bm_,
                           const float* __restrict__ Wv, const float* __restrict__ bv_) {
    int idx = blockIdx.x * 256 + threadIdx.x;
    if (idx < 40 * HDIM) {
        int n = idx / HDIM, k = idx % HDIM;
        float v = (n < ZDIM) ? Wm[k * ZDIM + n] : Wv[k * ZDIM + (n - ZDIM)];
        g_bth[idx] = __float2half_rn(v);
    }
    if (idx < 40) g_biash[idx] = (idx < ZDIM) ? bm_[idx] : bv_[idx - ZDIM];
}

// ---------------- mma.sync plain fp16 GEMM, double-buffered pipeline ----------
__device__ __forceinline__ void ldsm_x4(uint32_t r[4], uint32_t addr) {
    asm volatile("ldmatrix.sync.aligned.m8n8.x4.shared.b16 {%0,%1,%2,%3}, [%4];"
                 : "=r"(r[0]), "=r"(r[1]), "=r"(r[2]), "=r"(r[3]) : "r"(addr));
}
__device__ __forceinline__ void mma_f16(float c[4], const uint32_t a[4],
                                        const uint32_t b0, const uint32_t b1) {
    asm volatile("mma.sync.aligned.m16n8k16.row.col.f32.f16.f16.f32 "
                 "{%0,%1,%2,%3}, {%4,%5,%6,%7}, {%8,%9}, {%0,%1,%2,%3};"
                 : "+f"(c[0]), "+f"(c[1]), "+f"(c[2]), "+f"(c[3])
                 : "r"(a[0]), "r"(a[1]), "r"(a[2]), "r"(a[3]), "r"(b0), "r"(b1));
}
__device__ __forceinline__ void cp16(uint32_t dst, const void* src, int sz) {
    asm volatile("cp.async.cg.shared.global [%0], [%1], 16, %2;"
                 :: "r"(dst), "l"(src), "r"(sz));
}
__device__ __forceinline__ void cp_commit() { asm volatile("cp.async.commit_group;"); }
__device__ __forceinline__ void cp_wait0() { asm volatile("cp.async.wait_group 0;"); }

// dynamic smem: buffers of 128*40 f16 (10240B each)
#define SMS 5120
#define SMEM_BYTES (6 * SMS * 2)   // 61440 (covers both GEMM variants)

template <bool LOG1P, bool RELU, bool ROWSUM>
__global__ __launch_bounds__(256, 2)
void mma_gemm(const float* __restrict__ A,
              const __half* __restrict__ Bt,
              const float* __restrict__ bias,
              float* __restrict__ C, int M, int N, int K) {
    const int ST = 40;
    extern __shared__ __align__(16) __half dsm[];

    const int tid  = threadIdx.x;
    const int lane = tid & 31;
    const int warp = tid >> 5;
    const int wm = warp & 3;
    const int wn = warp >> 2;
    const int bm = blockIdx.y * 128, bn = blockIdx.x * 128;

    const uint32_t smem_base = (uint32_t)__cvta_generic_to_shared(dsm);

    float acc[2][8][4];
    #pragma unroll
    for (int mt = 0; mt < 2; mt++)
        #pragma unroll
        for (int nt = 0; nt < 8; nt++)
            #pragma unroll
            for (int q = 0; q < 4; q++) acc[mt][nt][q] = 0.f;

    float rsum[4] = {0.f, 0.f, 0.f, 0.f};

    const int a_row = wm * 32 + (lane & 15);
    const int a_k   = (lane >> 4) * 8;
    const int b_row = wn * 64 + ((lane >> 4) << 3) + (lane & 7);
    const int b_k   = ((lane >> 3) & 1) * 8;

    const int nkt = (K + 31) >> 5;

    auto ldgA = [&](int kt, float4 av[4]) {
        int k0 = kt << 5;
        #pragma unroll
        for (int i = 0; i < 4; i++) {
            int idx = tid + i * 256;
            int row = idx >> 3;
            int kw  = (idx & 7) << 2;
            int gm = bm + row, gk = k0 + kw;
            float4 v = make_float4(0.f, 0.f, 0.f, 0.f);
            if (gm < M && gk < K) v = *(const float4*)(A + (size_t)gm * K + gk);
            if (ROWSUM) rsum[i] += (v.x + v.y) + (v.z + v.w);
            av[i] = v;
        }
    };
    auto stoA = [&](const float4 av[4], int stage) {
        __half* dA = dsm + stage * 2 * SMS;
        #pragma unroll
        for (int i = 0; i < 4; i++) {
            float4 v = av[i];
            if (LOG1P) {
                v.x = __logf(1.f + v.x); v.y = __logf(1.f + v.y);
                v.z = __logf(1.f + v.z); v.w = __logf(1.f + v.w);
            }
            int idx = tid + i * 256;
            int row = idx >> 3;
            int kw  = (idx & 7) << 2;
            int off = row * ST + kw;
            *(uint32_t*)(dA + off)     = pack_h2(v.x, v.y);
            *(uint32_t*)(dA + off + 2) = pack_h2(v.z, v.w);
        }
    };
    auto ldB = [&](int kt, int stage) {
        int k0 = kt << 5;
        int n    = tid >> 1;
        int half = tid & 1;
        int gn = bn + n;
        const __half* srow = Bt + (size_t)gn * K + k0 + half * 16;
        uint32_t dstb = smem_base +
            (uint32_t)(((stage * 2 + 1) * SMS + n * ST + half * 16) * 2);
        #pragma unroll
        for (int j = 0; j < 2; j++) {
            int gk = k0 + half * 16 + j * 8;
            int sz = (gn < N && gk < K) ? 16 : 0;
            cp16(dstb + j * 16, srow + j * 8, sz);
        }
        cp_commit();
    };
    auto compute = [&](int stage) {
        const uint32_t bA = smem_base + (uint32_t)((stage * 2 + 0) * SMS * 2);
        const uint32_t bB = smem_base + (uint32_t)((stage * 2 + 1) * SMS * 2);
        #pragma unroll
        for (int ks = 0; ks < 2; ks++) {
            uint32_t ah0[4], ah1[4];
            {
                uint32_t o0 = (uint32_t)(((a_row) * ST + ks * 16 + a_k) * 2);
                uint32_t o1 = (uint32_t)(((a_row + 16) * ST + ks * 16 + a_k) * 2);
                ldsm_x4(ah0, bA + o0);
                ldsm_x4(ah1, bA + o1);
            }
            #pragma unroll
            for (int p = 0; p < 4; p++) {
                uint32_t o = (uint32_t)(((b_row + p * 16) * ST + ks * 16 + b_k) * 2);
                uint32_t rh[4];
                ldsm_x4(rh, bB + o);
                #pragma unroll
                for (int q = 0; q < 2; q++) {
                    int nt = 2 * p + q;
                    mma_f16(acc[0][nt], ah0, rh[2 * q], rh[2 * q + 1]);
                    mma_f16(acc[1][nt], ah1, rh[2 * q], rh[2 * q + 1]);
                }
            }
        }
    };

    // --- prologue: fill stage 0 ---
    float4 av[4];
    ldgA(0, av);
    ldB(0, 0);
    stoA(av, 0);
    cp_wait0();
    __syncthreads();

    // --- main pipelined loop ---
    int stage = 0;
    for (int kt = 0; kt < nkt; kt++) {
        const int nxt = stage ^ 1;
        const bool more = (kt + 1 < nkt);
        if (more) {
            ldgA(kt + 1, av);
            ldB(kt + 1, nxt);
        }
        compute(stage);
        if (more) {
            stoA(av, nxt);
            cp_wait0();
        }
        __syncthreads();
        stage = nxt;
    }

    if (ROWSUM) {
        #pragma unroll
        for (int i = 0; i < 4; i++) {
            float s = rsum[i];
            s += __shfl_down_sync(0xffffffffu, s, 4, 8);
            s += __shfl_down_sync(0xffffffffu, s, 2, 8);
            s += __shfl_down_sync(0xffffffffu, s, 1, 8);
            if ((lane & 7) == 0) {
                int row = bm + (tid >> 3) + i * 32;
                if (row < M) g_rowsum[row] = s;
            }
        }
    }

    // epilogue
    const int tg = lane >> 2;
    const int tc = (lane & 3) * 2;
    #pragma unroll
    for (int mt = 0; mt < 2; mt++) {
        int r0 = bm + wm * 32 + mt * 16 + tg;
        #pragma unroll
        for (int nt = 0; nt < 8; nt++) {
            int cn = bn + wn * 64 + nt * 8 + tc;
            if (cn >= N) continue;
            float2 bb = *(const float2*)(bias + cn);
            if (r0 < M) {
                float2 o;
                o.x = acc[mt][nt][0] + bb.x;
                o.y = acc[mt][nt][1] + bb.y;
                if (RELU) { o.x = fmaxf(o.x, 0.f); o.y = fmaxf(o.y, 0.f); }
                *(float2*)(C + (size_t)r0 * N + cn) = o;
            }
            if (r0 + 8 < M) {
                float2 o;
                o.x = acc[mt][nt][2] + bb.x;
                o.y = acc[mt][nt][3] + bb.y;
                if (RELU) { o.x = fmaxf(o.x, 0.f); o.y = fmaxf(o.y, 0.f); }
                *(float2*)(C + (size_t)(r0 + 8) * N + cn) = o;
            }
        }
    }
}

// ------- fused decoder GEMM + softmax*rowsum (one block owns 128 full rows) --
// smem: A 4 k-chunks (4*SMS) + B double buffer (2*SMS) = 6*SMS halves.
__global__ __launch_bounds__(256, 2)
void dec_fused(const float* __restrict__ A,
               const __half* __restrict__ Bt,
               const float* __restrict__ bias,
               float* __restrict__ C) {
    const int ST = 40;
    extern __shared__ __align__(16) __half dsm[];
    __shared__ float sexp[128];

    const int tid  = threadIdx.x;
    const int lane = tid & 31;
    const int warp = tid >> 5;
    const int wm = warp & 3;
    const int wn = warp >> 2;
    const int bm = blockIdx.x * 128;

    const uint32_t smem_base = (uint32_t)__cvta_generic_to_shared(dsm);

    if (tid < 128) sexp[tid] = 0.f;

    // ---- load A (hd) once: 4 k-chunks, fp32 -> fp16 ----
    #pragma unroll
    for (int kt = 0; kt < 4; kt++) {
        __half* dA = dsm + kt * SMS;
        #pragma unroll
        for (int i = 0; i < 4; i++) {
            int idx = tid + i * 256;
            int row = idx >> 3;
            int kw  = (idx & 7) << 2;
            int gm = bm + row;
            float4 v = make_float4(0.f, 0.f, 0.f, 0.f);
            if (gm < N_NODES) v = *(const float4*)(A + (size_t)gm * HDIM + kt * 32 + kw);
            int off = row * ST + kw;
            *(uint32_t*)(dA + off)     = pack_h2(v.x, v.y);
            *(uint32_t*)(dA + off + 2) = pack_h2(v.z, v.w);
        }
    }

    auto ldB = [&](int it, int stage) {
        int ntile = it >> 2, kt = it & 3;
        int n    = tid >> 1;
        int half = tid & 1;
        int gn = ntile * 128 + n;
        const __half* srow = Bt + (size_t)gn * HDIM + kt * 32 + half * 16;
        uint32_t dstb = smem_base +
            (uint32_t)(((4 + stage) * SMS + n * ST + half * 16) * 2);
        #pragma unroll
        for (int j = 0; j < 2; j++) {
            int sz = (gn < N_GENES) ? 16 : 0;
            cp16(dstb + j * 16, srow + j * 8, sz);
        }
        cp_commit();
    };

    const int a_row = wm * 32 + (lane & 15);
    const int a_k   = (lane >> 4) * 8;
    const int b_row = wn * 64 + ((lane >> 4) << 3) + (lane & 7);
    const int b_k   = ((lane >> 3) & 1) * 8;
    const int tg = lane >> 2;
    const int tc = (lane & 3) * 2;

    float acc[2][8][4];
    #pragma unroll
    for (int mt = 0; mt < 2; mt++)
        #pragma unroll
        for (int nt = 0; nt < 8; nt++)
            #pragma unroll
            for (int q = 0; q < 4; q++) acc[mt][nt][q] = 0.f;

    float es[4] = {0.f, 0.f, 0.f, 0.f};   // [mt*2 + half] row exp-sums

    ldB(0, 0);
    cp_wait0();
    __syncthreads();

    int stage = 0;
    for (int it = 0; it < 64; it++) {
        if (it + 1 < 64) ldB(it + 1, stage ^ 1);
        // compute: A chunk (it&3) x B stage
        {
            const uint32_t bA = smem_base + (uint32_t)((it & 3) * SMS * 2);
            const uint32_t bB = smem_base + (uint32_t)((4 + stage) * SMS * 2);
            #pragma unroll
            for (int ks = 0; ks < 2; ks++) {
                uint32_t ah0[4], ah1[4];
                {
                    uint32_t o0 = (uint32_t)(((a_row) * ST + ks * 16 + a_k) * 2);
                    uint32_t o1 = (uint32_t)(((a_row + 16) * ST + ks * 16 + a_k) * 2);
                    ldsm_x4(ah0, bA + o0);
                    ldsm_x4(ah1, bA + o1);
                }
                #pragma unroll
                for (int p = 0; p < 4; p++) {
                    uint32_t o = (uint32_t)(((b_row + p * 16) * ST + ks * 16 + b_k) * 2);
                    uint32_t rh[4];
                    ldsm_x4(rh, bB + o);
                    #pragma unroll
                    for (int q = 0; q < 2; q++) {
                        int nt = 2 * p + q;
                        mma_f16(acc[0][nt], ah0, rh[2 * q], rh[2 * q + 1]);
                        mma_f16(acc[1][nt], ah1, rh[2 * q], rh[2 * q + 1]);
                    }
                }
            }
        }
        if ((it & 3) == 3) {
            // tile epilogue: exp(logit) -> C, accumulate row exp-sums
            int bn = (it >> 2) * 128;
            #pragma unroll
            for (int mt = 0; mt < 2; mt++) {
                int r0 = bm + wm * 32 + mt * 16 + tg;
                #pragma unroll
                for (int nt = 0; nt < 8; nt++) {
                    int cn = bn + wn * 64 + nt * 8 + tc;
                    if (cn >= N_GENES) continue;
                    float2 bb = *(const float2*)(bias + cn);
                    float e0x = __expf(acc[mt][nt][0] + bb.x);
                    float e0y = __expf(acc[mt][nt][1] + bb.y);
                    float e1x = __expf(acc[mt][nt][2] + bb.x);
                    float e1y = __expf(acc[mt][nt][3] + bb.y);
                    if (r0 < N_NODES) {
                        *(float2*)(C + (size_t)r0 * N_GENES + cn) = make_float2(e0x, e0y);
                        es[mt * 2 + 0] += e0x + e0y;
                    }
                    if (r0 + 8 < N_NODES) {
                        *(float2*)(C + (size_t)(r0 + 8) * N_GENES + cn) = make_float2(e1x, e1y);
                        es[mt * 2 + 1] += e1x + e1y;
                    }
                }
            }
            #pragma unroll
            for (int mt = 0; mt < 2; mt++)
                #pragma unroll
                for (int nt = 0; nt < 8; nt++)
                    #pragma unroll
                    for (int q = 0; q < 4; q++) acc[mt][nt][q] = 0.f;
        }
        cp_wait0();
        __syncthreads();
        stage ^= 1;
    }

    // reduce exp-sums: lanes sharing a row differ in (lane&3); then cross-warp
    #pragma unroll
    for (int i = 0; i < 4; i++) {
        es[i] += __shfl_xor_sync(0xffffffffu, es[i], 1);
        es[i] += __shfl_xor_sync(0xffffffffu, es[i], 2);
    }
    if ((lane & 3) == 0) {
        #pragma unroll
        for (int mt = 0; mt < 2; mt++) {
            int lr = wm * 32 + mt * 16 + tg;
            atomicAdd(&sexp[lr], es[mt * 2 + 0]);
            atomicAdd(&sexp[lr + 8], es[mt * 2 + 1]);
        }
    }
    __syncthreads();

    // scale pass: re-read own exp values (L2) and write final px_rate
    #pragma unroll
    for (int mt = 0; mt < 2; mt++) {
        int r0 = bm + wm * 32 + mt * 16 + tg;
        float s0 = 0.f, s1 = 0.f;
        if (r0 < N_NODES)     s0 = g_rowsum[r0] / sexp[r0 - bm];
        if (r0 + 8 < N_NODES) s1 = g_rowsum[r0 + 8] / sexp[r0 + 8 - bm];
        for (int ntile = 0; ntile < 16; ntile++) {
            #pragma unroll
            for (int nt = 0; nt < 8; nt++) {
                int cn = ntile * 128 + wn * 64 + nt * 8 + tc;
                if (cn >= N_GENES) continue;
                if (r0 < N_NODES) {
                    float2 v = *(float2*)(C + (size_t)r0 * N_GENES + cn);
                    v.x *= s0; v.y *= s0;
                    *(float2*)(C + (size_t)r0 * N_GENES + cn) = v;
                }
                if (r0 + 8 < N_NODES) {
                    float2 v = *(float2*)(C + (size_t)(r0 + 8) * N_GENES + cn);
                    v.x *= s1; v.y *= s1;
                    *(float2*)(C + (size_t)(r0 + 8) * N_GENES + cn) = v;
                }
            }
        }
    }
}

// -- GAT prep (merged zfeat): z -> zall, feat -> fp16 xl/xr projections --------
__global__ __launch_bounds__(256)
void gat_pre(const float* __restrict__ eps_z,
             const float* __restrict__ Wlm, const float* __restrict__ blm,
             const float* __restrict__ Wrm, const float* __restrict__ brm,
             const float* __restrict__ Wlv, const float* __restrict__ blv,
             const float* __restrict__ Wrv, const float* __restrict__ brv) {
    __shared__ float s[440];
    int tid = threadIdx.x;
    if (tid < 100) { s[tid] = Wlm[tid]; s[100 + tid] = Wrm[tid];
                     s[200 + tid] = Wlv[tid]; s[300 + tid] = Wrv[tid]; }
    if (tid < 10)  { s[400 + tid] = blm[tid]; s[410 + tid] = brm[tid];
                     s[420 + tid] = blv[tid]; s[430 + tid] = brv[tid]; }
    __syncthreads();
    int n = blockIdx.x * 256 + tid;
    if (n >= N_NODES) return;

    // reparameterize z into zall[10..30), keep feat = q_m[10..20) in regs
    float f[SDIM];
    #pragma unroll
    for (int c = 0; c < ZDIM; c++) {
        float qm  = g_qmv[(size_t)n * 40 + c];
        float qvr = g_qmv[(size_t)n * 40 + ZDIM + c];
        float z = qm + sqrtf(__expf(qvr) + VAR_EPS) * eps_z[(size_t)n * ZDIM + c];
        g_zall[(size_t)n * 30 + SDIM + c] = z;
        if (c >= SDIM) f[c - SDIM] = qm;
    }
    #pragma unroll
    for (int c = 0; c < SDIM; c++) {
        float lm = s[400 + c], rm = s[410 + c], lv = s[420 + c], rv = s[430 + c];
        #pragma unroll
        for (int k = 0; k < SDIM; k++) {
            lm += f[k] * s[k * 10 + c];
            rm += f[k] * s[100 + k * 10 + c];
            lv += f[k] * s[200 + k * 10 + c];
            rv += f[k] * s[300 + k * 10 + c];
        }
        g_xlh[(size_t)n * 24 + c]      = __float2half_rn(lm);
        g_xlh[(size_t)n * 24 + 10 + c] = __float2half_rn(lv);
        g_xrh[(size_t)n * 24 + c]      = __float2half_rn(rm);
        g_xrh[(size_t)n * 24 + 10 + c] = __float2half_rn(rv);
    }
}

__global__ __launch_bounds__(256) void gat_init() {
    int n = blockIdx.x * 256 + threadIdx.x;
    if (n >= N_NODES) return;
    g_sum2[n] = make_float2(0.f, 0.f);
    float4* p = (float4*)(g_num + (size_t)n * 20);
    #pragma unroll
    for (int j = 0; j < 5; j++) p[j] = make_float4(0.f, 0.f, 0.f, 0.f);
}

// single fused edge pass: fp16 feature loads, fp32 vector reductions
__global__ __launch_bounds__(256)
void gat_edge(const int* __restrict__ src, const int* __restrict__ dst,
              const float* __restrict__ attm, const float* __restrict__ attv) {
    __shared__ float sa[20];
    if (threadIdx.x < SDIM) { sa[threadIdx.x] = attm[threadIdx.x];
                              sa[10 + threadIdx.x] = attv[threadIdx.x]; }
    __syncthreads();
    int e = blockIdx.x * 256 + threadIdx.x;
    if (e >= N_EDGES) return;
    int s = src[e], d = dst[e];

    float xs[20], xd[20];
    ld20h(g_xlh + (size_t)s * 24, xs);
    ld20h(g_xrh + (size_t)d * 24, xd);

    float am = 0.f, av = 0.f;
    #pragma unroll
    for (int i = 0; i < SDIM; i++) {
        float tm = xs[i] + xd[i];
        tm = tm > 0.f ? tm : 0.2f * tm;
        am += tm * sa[i];
        float tv = xs[10 + i] + xd[10 + i];
        tv = tv > 0.f ? tv : 0.2f * tv;
        av += tv * sa[10 + i];
    }
    float eem = __expf(am);
    float eev = __expf(av);

    red_v2(&g_sum2[d], eem, eev);
    float* nb = g_num + (size_t)d * 20;
    #pragma unroll
    for (int j = 0; j < 5; j++) {
        float w0 = ((4 * j + 0) < 10 ? eem : eev) * xs[4 * j + 0];
        float w1 = ((4 * j + 1) < 10 ? eem : eev) * xs[4 * j + 1];
        float w2 = ((4 * j + 2) < 10 ? eem : eev) * xs[4 * j + 2];
        float w3 = ((4 * j + 3) < 10 ? eem : eev) * xs[4 * j + 3];
        red_v4(nb + 4 * j, w0, w1, w2, w3);
    }
}

// finalize GAT heads -> z_all[0..10) (z already written by gat_pre)
__global__ __launch_bounds__(256)
void gat_fin(const float* __restrict__ bias_m, const float* __restrict__ bias_v,
             const float* __restrict__ eps_gat) {
    int n = blockIdx.x * 256 + threadIdx.x;
    if (n >= N_NODES) return;
    float2 s2 = g_sum2[n];
    float ism = 1.f / (s2.x + 1e-16f);
    float isv = 1.f / (s2.y + 1e-16f);
    #pragma unroll
    for (int i = 0; i < SDIM; i++) {
        float qm = g_num[(size_t)n * 20 + i] * ism + bias_m[i];
        float pv = g_num[(size_t)n * 20 + 10 + i] * isv + bias_v[i];
        float qv = __expf(pv) + VAR_EPS;
        g_zall[(size_t)n * 30 + i] = qm + sqrtf(qv) * eps_gat[(size_t)n * SDIM + i];
    }
}

// ---------------- decoder layer 0 + LayerNorm + relu (1 warp / row) ----------
__global__ __launch_bounds__(256)
void dec0_ln(const float* __restrict__ W0, const float* __restrict__ b0) {
    __shared__ float sW[30 * HDIM];
    __shared__ float sb[HDIM];
    __shared__ float sz[8][32];
    int tid = threadIdx.x;
    for (int i = tid; i < 30 * HDIM; i += 256) sW[i] = W0[i];
    if (tid < HDIM) sb[tid] = b0[tid];
    int warp = tid >> 5, lane = tid & 31;
    int r = blockIdx.x * 8 + warp;
    if (r < N_NODES && lane < 30) sz[warp][lane] = g_zall[(size_t)r * 30 + lane];
    __syncthreads();
    if (r >= N_NODES) return;
    float v[4];
    #pragma unroll
    for (int q = 0; q < 4; q++) {
        int c = lane + 32 * q;
        float a = sb[c];
        #pragma unroll
        for (int k = 0; k < 30; k++) a += sz[warp][k] * sW[k * HDIM + c];
        v[q] = a;
    }
    float s  = v[0] + v[1] + v[2] + v[3];
    float ss = v[0] * v[0] + v[1] * v[1] + v[2] * v[2] + v[3] * v[3];
    #pragma unroll
    for (int o = 16; o; o >>= 1) {
        s  += __shfl_xor_sync(0xffffffffu, s,  o);
        ss += __shfl_xor_sync(0xffffffffu, ss, o);
    }
    float mean = s * (1.f / 128.f);
    float var  = ss * (1.f / 128.f) - mean * mean;
    float inv  = rsqrtf(var + 1e-5f);
    #pragma unroll
    for (int q = 0; q < 4; q++) {
        float o_ = (v[q] - mean) * inv;
        g_hd[(size_t)r * HDIM + lane + 32 * q] = fmaxf(o_, 0.f);
    }
}

// -----------------------------------------------------------------------------
extern "C" void kernel_launch(void* const* d_in, const int* in_sizes, int n_in,
                              void* d_out, int out_size) {
    const float* x       = (const float*)d_in[0];
    const int*   ei      = (const int*)d_in[1];
    const float* eps_z   = (const float*)d_in[3];
    const float* eps_gat = (const float*)d_in[4];
    const float* enc_W0  = (const float*)d_in[5];
    const float* enc_b0  = (const float*)d_in[6];
    const float* enc_W1  = (const float*)d_in[7];
    const float* enc_b1  = (const float*)d_in[8];
    const float* enc_Wm  = (const float*)d_in[9];
    const float* enc_bm  = (const float*)d_in[10];
    const float* enc_Wv  = (const float*)d_in[11];
    const float* enc_bv  = (const float*)d_in[12];
    const float* gm_Wl   = (const float*)d_in[13];
    const float* gm_bl   = (const float*)d_in[14];
    const float* gm_Wr   = (const float*)d_in[15];
    const float* gm_br   = (const float*)d_in[16];
    const float* gm_att  = (const float*)d_in[17];
    const float* gm_bias = (const float*)d_in[18];
    const float* gv_Wl   = (const float*)d_in[19];
    const float* gv_bl   = (const float*)d_in[20];
    const float* gv_Wr   = (const float*)d_in[21];
    const float* gv_br   = (const float*)d_in[22];
    const float* gv_att  = (const float*)d_in[23];
    const float* gv_bias = (const float*)d_in[24];
    const float* dec_W0  = (const float*)d_in[25];
    const float* dec_b0  = (const float*)d_in[26];
    const float* dec_Ws  = (const float*)d_in[27];
    const float* dec_bs  = (const float*)d_in[28];
    float* out = (float*)d_out;

    const int* e_src = ei;
    const int* e_dst = ei + N_EDGES;

    float *p_h0, *p_h1, *p_hd, *p_qmv, *p_biash;
    __half *p_bt0, *p_bt1, *p_btd, *p_bth;
    cudaGetSymbolAddress((void**)&p_h0, g_h0);
    cudaGetSymbolAddress((void**)&p_h1, g_h1);
    cudaGetSymbolAddress((void**)&p_hd, g_hd);
    cudaGetSymbolAddress((void**)&p_qmv, g_qmv);
    cudaGetSymbolAddress((void**)&p_biash, g_biash);
    cudaGetSymbolAddress((void**)&p_bt0, g_bt0);
    cudaGetSymbolAddress((void**)&p_bt1, g_bt1);
    cudaGetSymbolAddress((void**)&p_btd, g_btd);
    cudaGetSymbolAddress((void**)&p_bth, g_bth);

    cudaFuncSetAttribute(mma_gemm<true, true, true>,
                         cudaFuncAttributeMaxDynamicSharedMemorySize, SMEM_BYTES);
    cudaFuncSetAttribute(mma_gemm<false, true, false>,
                         cudaFuncAttributeMaxDynamicSharedMemorySize, SMEM_BYTES);
    cudaFuncSetAttribute(mma_gemm<false, false, false>,
                         cudaFuncAttributeMaxDynamicSharedMemorySize, SMEM_BYTES);
    cudaFuncSetAttribute(dec_fused,
                         cudaFuncAttributeMaxDynamicSharedMemorySize, SMEM_BYTES);

    const int MB = (N_NODES + 127) / 128;  // 235

    // weight prep (enc0 GEMM stays the 4th launch -> ncu slot)
    transpose_split<<<dim3(4, 63), dim3(32, 8)>>>(enc_W0, p_bt0, N_GENES, HDIM);
    transpose_split<<<dim3(4, 4),  dim3(32, 8)>>>(enc_W1, p_bt1, HDIM, HDIM);
    prep_heads<<<20, 256>>>(enc_Wm, enc_bm, enc_Wv, enc_bv);

    // encoder layer 0 (fused rowsum + log1p): h0 = relu(log1p(x) @ W0 + b0)
    mma_gemm<true, true, true><<<dim3(1, MB), 256, SMEM_BYTES>>>(
        x, p_bt0, enc_b0, p_h0, N_NODES, HDIM, N_GENES);
    // encoder layer 1
    mma_gemm<false, true, false><<<dim3(1, MB), 256, SMEM_BYTES>>>(
        p_h0, p_bt1, enc_b1, p_h1, N_NODES, HDIM, HDIM);
    // heads as GEMM: qmv[:, :20] = q_m, qmv[:, 20:] = pre-exp q_v
    mma_gemm<false, false, false><<<dim3(1, MB), 256, SMEM_BYTES>>>(
        p_h1, p_bth, p_biash, p_qmv, N_NODES, 40, HDIM);

    // GAT prep (merged z reparam + projections), init, edge pass, finalize
    gat_pre<<<(N_NODES + 255) / 256, 256>>>(eps_z, gm_Wl, gm_bl, gm_Wr, gm_br,
                                            gv_Wl, gv_bl, gv_Wr, gv_br);
    gat_init<<<(N_NODES + 255) / 256, 256>>>();
    transpose_split<<<dim3(63, 4), dim3(32, 8)>>>(dec_Ws, p_btd, HDIM, N_GENES);
    gat_edge<<<(N_EDGES + 255) / 256, 256>>>(e_src, e_dst, gm_att, gv_att);
    gat_fin<<<(N_NODES + 255) / 256, 256>>>(gm_bias, gv_bias, eps_gat);

    // decoder layer 0 + LN + relu
    dec0_ln<<<(N_NODES + 7) / 8, 256>>>(dec_W0, dec_b0);

    // fused decoder GEMM + softmax * rowsum straight into d_out
    dec_fused<<<MB, 256, SMEM_BYTES>>>(p_hd, p_btd, dec_bs, out);
}

// round 17
// speedup vs baseline: 1.3439x; 1.3439x over previous
#include <cuda_runtime.h>
#include <cuda_fp16.h>
#include <stdint.h>
#include <math.h>

#define N_NODES 30000
#define N_GENES 2000
#define HDIM    128
#define ZDIM    20
#define SDIM    10
#define N_EDGES 960000
#define VAR_EPS 1e-4f

// ---------------- scratch (static device globals; no allocations) ------------
__device__ __align__(16) float g_h0[N_NODES * HDIM];
__device__ __align__(16) float g_h1[N_NODES * HDIM];
__device__ __align__(16) float g_qmv[N_NODES * 40];
__device__ __align__(16) __half g_xlh[N_NODES * 24];   // [m(10)|v(10)|pad(4)]
__device__ __align__(16) __half g_xrh[N_NODES * 24];
__device__ __align__(16) float g_num[N_NODES * 20];
__device__ __align__(8)  float2 g_sum2[N_NODES];
__device__ __align__(16) float g_zall[N_NODES * 30];
__device__ __align__(16) float g_hd[N_NODES * HDIM];
__device__ float g_rowsum[N_NODES];

// fp16 weight buffers, transposed to [N][K]
__device__ __align__(16) __half g_bt0[HDIM * N_GENES];
__device__ __align__(16) __half g_bt1[HDIM * HDIM];
__device__ __align__(16) __half g_bth[40 * HDIM];
__device__ __align__(16) __half g_btd[N_GENES * HDIM];
__device__ float g_biash[40];

// ---------------- vector reductions (sm_90+) ----------------------------------
__device__ __forceinline__ void red_v2(float2* p, float a, float b) {
    asm volatile("red.global.add.v2.f32 [%0], {%1,%2};"
                 :: "l"(p), "f"(a), "f"(b) : "memory");
}
__device__ __forceinline__ void red_v4(float* p, float a, float b, float c, float d) {
    asm volatile("red.global.add.v4.f32 [%0], {%1,%2,%3,%4};"
                 :: "l"(p), "f"(a), "f"(b), "f"(c), "f"(d) : "memory");
}

// ---------------- fp16 helpers ------------------------------------------------
__device__ __forceinline__ uint32_t pack_h2(float a, float b) {
    uint32_t r;
    asm("cvt.rn.f16x2.f32 %0, %2, %1;" : "=r"(r) : "f"(a), "f"(b));
    return r;
}
// unpack 20 floats from a 24-half padded row (aligned vector loads)
__device__ __forceinline__ void ld20h(const __half* p, float x[20]) {
    const uint4* q = (const uint4*)p;
    uint4 a = q[0], b = q[1];
    uint32_t w[10];
    w[0] = a.x; w[1] = a.y; w[2] = a.z; w[3] = a.w;
    w[4] = b.x; w[5] = b.y; w[6] = b.z; w[7] = b.w;
    uint2 c = *(const uint2*)(p + 16);
    w[8] = c.x; w[9] = c.y;
    #pragma unroll
    for (int i = 0; i < 10; i++) {
        float2 f = __half22float2(*(__half2*)&w[i]);
        x[2 * i] = f.x; x[2 * i + 1] = f.y;
    }
}

// ---------------- weight transpose: B[K][N] -> T[N][K] fp16 ------------------
__global__ void transpose_split(const float* __restrict__ B,
                                __half* __restrict__ Th,
                                int K, int N) {
    __shared__ float tile[32][33];
    int kb = blockIdx.y * 32, nb = blockIdx.x * 32;
    for (int i = threadIdx.y; i < 32; i += 8) {
        int k = kb + i, n = nb + threadIdx.x;
        tile[i][threadIdx.x] = (k < K && n < N) ? B[(size_t)k * N + n] : 0.f;
    }
    __syncthreads();
    for (int i = threadIdx.y; i < 32; i += 8) {
        int n = nb + i, k = kb + threadIdx.x;
        if (n < N && k < K)
            Th[(size_t)n * K + k] = __float2half_rn(tile[threadIdx.x][i]);
    }
}

// concat [Wm | Wv] (each HDIM x ZDIM) into head weight T[40][128] + bias[40]
__global__ void prep_heads(const float* __restrict__ Wm, const float* __restrict__ bm_,
                           const float* __restrict__ Wv, const float* __restrict__ bv_) {
    int idx = blockIdx.x * 256 + threadIdx.x;
    if (idx < 40 * HDIM) {
        int n = idx / HDIM, k = idx % HDIM;
        float v = (n < ZDIM) ? Wm[k * ZDIM + n] : Wv[k * ZDIM + (n - ZDIM)];
        g_bth[idx] = __float2half_rn(v);
    }
    if (idx < 40) g_biash[idx] = (idx < ZDIM) ? bm_[idx] : bv_[idx - ZDIM];
}

// ---------------- mma.sync plain fp16 GEMM, double-buffered pipeline ----------
__device__ __forceinline__ void ldsm_x4(uint32_t r[4], uint32_t addr) {
    asm volatile("ldmatrix.sync.aligned.m8n8.x4.shared.b16 {%0,%1,%2,%3}, [%4];"
                 : "=r"(r[0]), "=r"(r[1]), "=r"(r[2]), "=r"(r[3]) : "r"(addr));
}
__device__ __forceinline__ void mma_f16(float c[4], const uint32_t a[4],
                                        const uint32_t b0, const uint32_t b1) {
    asm volatile("mma.sync.aligned.m16n8k16.row.col.f32.f16.f16.f32 "
                 "{%0,%1,%2,%3}, {%4,%5,%6,%7}, {%8,%9}, {%0,%1,%2,%3};"
                 : "+f"(c[0]), "+f"(c[1]), "+f"(c[2]), "+f"(c[3])
                 : "r"(a[0]), "r"(a[1]), "r"(a[2]), "r"(a[3]), "r"(b0), "r"(b1));
}
__device__ __forceinline__ void cp16(uint32_t dst, const void* src, int sz) {
    asm volatile("cp.async.cg.shared.global [%0], [%1], 16, %2;"
                 :: "r"(dst), "l"(src), "r"(sz));
}
__device__ __forceinline__ void cp_commit() { asm volatile("cp.async.commit_group;"); }
__device__ __forceinline__ void cp_wait0() { asm volatile("cp.async.wait_group 0;"); }

// dynamic smem: 4 buffers of 128*40 f16: (stage*2 + {0:A, 1:B})*SMS
#define SMS 5120
#define SMEM_BYTES (4 * SMS * 2)

template <bool LOG1P, bool RELU, bool ROWSUM>
__global__ __launch_bounds__(256, 2)
void mma_gemm(const float* __restrict__ A,
              const __half* __restrict__ Bt,
              const float* __restrict__ bias,
              float* __restrict__ C, int M, int N, int K) {
    const int ST = 40;
    extern __shared__ __align__(16) __half dsm[];

    const int tid  = threadIdx.x;
    const int lane = tid & 31;
    const int warp = tid >> 5;
    const int wm = warp & 3;
    const int wn = warp >> 2;
    const int bm = blockIdx.y * 128, bn = blockIdx.x * 128;

    const uint32_t smem_base = (uint32_t)__cvta_generic_to_shared(dsm);

    float acc[2][8][4];
    #pragma unroll
    for (int mt = 0; mt < 2; mt++)
        #pragma unroll
        for (int nt = 0; nt < 8; nt++)
            #pragma unroll
            for (int q = 0; q < 4; q++) acc[mt][nt][q] = 0.f;

    float rsum[4] = {0.f, 0.f, 0.f, 0.f};

    const int a_row = wm * 32 + (lane & 15);
    const int a_k   = (lane >> 4) * 8;
    const int b_row = wn * 64 + ((lane >> 4) << 3) + (lane & 7);
    const int b_k   = ((lane >> 3) & 1) * 8;

    const int nkt = (K + 31) >> 5;

    auto ldgA = [&](int kt, float4 av[4]) {
        int k0 = kt << 5;
        #pragma unroll
        for (int i = 0; i < 4; i++) {
            int idx = tid + i * 256;
            int row = idx >> 3;
            int kw  = (idx & 7) << 2;
            int gm = bm + row, gk = k0 + kw;
            float4 v = make_float4(0.f, 0.f, 0.f, 0.f);
            if (gm < M && gk < K) v = *(const float4*)(A + (size_t)gm * K + gk);
            if (ROWSUM) rsum[i] += (v.x + v.y) + (v.z + v.w);
            av[i] = v;
        }
    };
    auto stoA = [&](const float4 av[4], int stage) {
        __half* dA = dsm + stage * 2 * SMS;
        #pragma unroll
        for (int i = 0; i < 4; i++) {
            float4 v = av[i];
            if (LOG1P) {
                v.x = __logf(1.f + v.x); v.y = __logf(1.f + v.y);
                v.z = __logf(1.f + v.z); v.w = __logf(1.f + v.w);
            }
            int idx = tid + i * 256;
            int row = idx >> 3;
            int kw  = (idx & 7) << 2;
            int off = row * ST + kw;
            *(uint32_t*)(dA + off)     = pack_h2(v.x, v.y);
            *(uint32_t*)(dA + off + 2) = pack_h2(v.z, v.w);
        }
    };
    auto ldB = [&](int kt, int stage) {
        int k0 = kt << 5;
        int n    = tid >> 1;
        int half = tid & 1;
        int gn = bn + n;
        const __half* srow = Bt + (size_t)gn * K + k0 + half * 16;
        uint32_t dstb = smem_base +
            (uint32_t)(((stage * 2 + 1) * SMS + n * ST + half * 16) * 2);
        #pragma unroll
        for (int j = 0; j < 2; j++) {
            int gk = k0 + half * 16 + j * 8;
            int sz = (gn < N && gk < K) ? 16 : 0;
            cp16(dstb + j * 16, srow + j * 8, sz);
        }
        cp_commit();
    };
    auto compute = [&](int stage) {
        const uint32_t bA = smem_base + (uint32_t)((stage * 2 + 0) * SMS * 2);
        const uint32_t bB = smem_base + (uint32_t)((stage * 2 + 1) * SMS * 2);
        #pragma unroll
        for (int ks = 0; ks < 2; ks++) {
            uint32_t ah0[4], ah1[4];
            {
                uint32_t o0 = (uint32_t)(((a_row) * ST + ks * 16 + a_k) * 2);
                uint32_t o1 = (uint32_t)(((a_row + 16) * ST + ks * 16 + a_k) * 2);
                ldsm_x4(ah0, bA + o0);
                ldsm_x4(ah1, bA + o1);
            }
            #pragma unroll
            for (int p = 0; p < 4; p++) {
                uint32_t o = (uint32_t)(((b_row + p * 16) * ST + ks * 16 + b_k) * 2);
                uint32_t rh[4];
                ldsm_x4(rh, bB + o);
                #pragma unroll
                for (int q = 0; q < 2; q++) {
                    int nt = 2 * p + q;
                    mma_f16(acc[0][nt], ah0, rh[2 * q], rh[2 * q + 1]);
                    mma_f16(acc[1][nt], ah1, rh[2 * q], rh[2 * q + 1]);
                }
            }
        }
    };

    // --- prologue: fill stage 0 ---
    float4 av[4];
    ldgA(0, av);
    ldB(0, 0);
    stoA(av, 0);
    cp_wait0();
    __syncthreads();

    // --- main pipelined loop ---
    int stage = 0;
    for (int kt = 0; kt < nkt; kt++) {
        const int nxt = stage ^ 1;
        const bool more = (kt + 1 < nkt);
        if (more) {
            ldgA(kt + 1, av);
            ldB(kt + 1, nxt);
        }
        compute(stage);
        if (more) {
            stoA(av, nxt);
            cp_wait0();
        }
        __syncthreads();
        stage = nxt;
    }

    if (ROWSUM) {
        #pragma unroll
        for (int i = 0; i < 4; i++) {
            float s = rsum[i];
            s += __shfl_down_sync(0xffffffffu, s, 4, 8);
            s += __shfl_down_sync(0xffffffffu, s, 2, 8);
            s += __shfl_down_sync(0xffffffffu, s, 1, 8);
            if ((lane & 7) == 0) {
                int row = bm + (tid >> 3) + i * 32;
                if (row < M) g_rowsum[row] = s;
            }
        }
    }

    // epilogue
    const int tg = lane >> 2;
    const int tc = (lane & 3) * 2;
    #pragma unroll
    for (int mt = 0; mt < 2; mt++) {
        int r0 = bm + wm * 32 + mt * 16 + tg;
        #pragma unroll
        for (int nt = 0; nt < 8; nt++) {
            int cn = bn + wn * 64 + nt * 8 + tc;
            if (cn >= N) continue;
            float2 bb = *(const float2*)(bias + cn);
            if (r0 < M) {
                float2 o;
                o.x = acc[mt][nt][0] + bb.x;
                o.y = acc[mt][nt][1] + bb.y;
                if (RELU) { o.x = fmaxf(o.x, 0.f); o.y = fmaxf(o.y, 0.f); }
                *(float2*)(C + (size_t)r0 * N + cn) = o;
            }
            if (r0 + 8 < M) {
                float2 o;
                o.x = acc[mt][nt][2] + bb.x;
                o.y = acc[mt][nt][3] + bb.y;
                if (RELU) { o.x = fmaxf(o.x, 0.f); o.y = fmaxf(o.y, 0.f); }
                *(float2*)(C + (size_t)(r0 + 8) * N + cn) = o;
            }
        }
    }
}

// -- GAT prep (merged zfeat + init): z -> zall, projections -> fp16, zero accum
__global__ __launch_bounds__(256)
void gat_pre(const float* __restrict__ eps_z,
             const float* __restrict__ Wlm, const float* __restrict__ blm,
             const float* __restrict__ Wrm, const float* __restrict__ brm,
             const float* __restrict__ Wlv, const float* __restrict__ blv,
             const float* __restrict__ Wrv, const float* __restrict__ brv) {
    __shared__ float s[440];
    int tid = threadIdx.x;
    if (tid < 100) { s[tid] = Wlm[tid]; s[100 + tid] = Wrm[tid];
                     s[200 + tid] = Wlv[tid]; s[300 + tid] = Wrv[tid]; }
    if (tid < 10)  { s[400 + tid] = blm[tid]; s[410 + tid] = brm[tid];
                     s[420 + tid] = blv[tid]; s[430 + tid] = brv[tid]; }
    __syncthreads();
    int n = blockIdx.x * 256 + tid;
    if (n >= N_NODES) return;

    // zero accumulators for the edge pass
    g_sum2[n] = make_float2(0.f, 0.f);
    float4* pz = (float4*)(g_num + (size_t)n * 20);
    #pragma unroll
    for (int j = 0; j < 5; j++) pz[j] = make_float4(0.f, 0.f, 0.f, 0.f);

    // reparameterize z into zall[10..30), keep feat = q_m[10..20) in regs
    float f[SDIM];
    #pragma unroll
    for (int c = 0; c < ZDIM; c++) {
        float qm  = g_qmv[(size_t)n * 40 + c];
        float qvr = g_qmv[(size_t)n * 40 + ZDIM + c];
        float z = qm + sqrtf(__expf(qvr) + VAR_EPS) * eps_z[(size_t)n * ZDIM + c];
        g_zall[(size_t)n * 30 + SDIM + c] = z;
        if (c >= SDIM) f[c - SDIM] = qm;
    }
    #pragma unroll
    for (int c = 0; c < SDIM; c++) {
        float lm = s[400 + c], rm = s[410 + c], lv = s[420 + c], rv = s[430 + c];
        #pragma unroll
        for (int k = 0; k < SDIM; k++) {
            lm += f[k] * s[k * 10 + c];
            rm += f[k] * s[100 + k * 10 + c];
            lv += f[k] * s[200 + k * 10 + c];
            rv += f[k] * s[300 + k * 10 + c];
        }
        g_xlh[(size_t)n * 24 + c]      = __float2half_rn(lm);
        g_xlh[(size_t)n * 24 + 10 + c] = __float2half_rn(lv);
        g_xrh[(size_t)n * 24 + c]      = __float2half_rn(rm);
        g_xrh[(size_t)n * 24 + 10 + c] = __float2half_rn(rv);
    }
}

// single fused edge pass: fp16 feature loads, fp32 vector reductions
__global__ __launch_bounds__(256)
void gat_edge(const int* __restrict__ src, const int* __restrict__ dst,
              const float* __restrict__ attm, const float* __restrict__ attv) {
    __shared__ float sa[20];
    if (threadIdx.x < SDIM) { sa[threadIdx.x] = attm[threadIdx.x];
                              sa[10 + threadIdx.x] = attv[threadIdx.x]; }
    __syncthreads();
    int e = blockIdx.x * 256 + threadIdx.x;
    if (e >= N_EDGES) return;
    int s = src[e], d = dst[e];

    float xs[20], xd[20];
    ld20h(g_xlh + (size_t)s * 24, xs);
    ld20h(g_xrh + (size_t)d * 24, xd);

    float am = 0.f, av = 0.f;
    #pragma unroll
    for (int i = 0; i < SDIM; i++) {
        float tm = xs[i] + xd[i];
        tm = tm > 0.f ? tm : 0.2f * tm;
        am += tm * sa[i];
        float tv = xs[10 + i] + xd[10 + i];
        tv = tv > 0.f ? tv : 0.2f * tv;
        av += tv * sa[10 + i];
    }
    float eem = __expf(am);
    float eev = __expf(av);

    red_v2(&g_sum2[d], eem, eev);
    float* nb = g_num + (size_t)d * 20;
    #pragma unroll
    for (int j = 0; j < 5; j++) {
        float w0 = ((4 * j + 0) < 10 ? eem : eev) * xs[4 * j + 0];
        float w1 = ((4 * j + 1) < 10 ? eem : eev) * xs[4 * j + 1];
        float w2 = ((4 * j + 2) < 10 ? eem : eev) * xs[4 * j + 2];
        float w3 = ((4 * j + 3) < 10 ? eem : eev) * xs[4 * j + 3];
        red_v4(nb + 4 * j, w0, w1, w2, w3);
    }
}

// finalize GAT heads -> z_all[0..10) (z already written by gat_pre)
__global__ __launch_bounds__(256)
void gat_fin(const float* __restrict__ bias_m, const float* __restrict__ bias_v,
             const float* __restrict__ eps_gat) {
    int n = blockIdx.x * 256 + threadIdx.x;
    if (n >= N_NODES) return;
    float2 s2 = g_sum2[n];
    float ism = 1.f / (s2.x + 1e-16f);
    float isv = 1.f / (s2.y + 1e-16f);
    #pragma unroll
    for (int i = 0; i < SDIM; i++) {
        float qm = g_num[(size_t)n * 20 + i] * ism + bias_m[i];
        float pv = g_num[(size_t)n * 20 + 10 + i] * isv + bias_v[i];
        float qv = __expf(pv) + VAR_EPS;
        g_zall[(size_t)n * 30 + i] = qm + sqrtf(qv) * eps_gat[(size_t)n * SDIM + i];
    }
}

// ---------------- decoder layer 0 + LayerNorm + relu (1 warp / row) ----------
__global__ __launch_bounds__(256)
void dec0_ln(const float* __restrict__ W0, const float* __restrict__ b0) {
    __shared__ float sW[30 * HDIM];
    __shared__ float sb[HDIM];
    __shared__ float sz[8][32];
    int tid = threadIdx.x;
    for (int i = tid; i < 30 * HDIM; i += 256) sW[i] = W0[i];
    if (tid < HDIM) sb[tid] = b0[tid];
    int warp = tid >> 5, lane = tid & 31;
    int r = blockIdx.x * 8 + warp;
    if (r < N_NODES && lane < 30) sz[warp][lane] = g_zall[(size_t)r * 30 + lane];
    __syncthreads();
    if (r >= N_NODES) return;
    float v[4];
    #pragma unroll
    for (int q = 0; q < 4; q++) {
        int c = lane + 32 * q;
        float a = sb[c];
        #pragma unroll
        for (int k = 0; k < 30; k++) a += sz[warp][k] * sW[k * HDIM + c];
        v[q] = a;
    }
    float s  = v[0] + v[1] + v[2] + v[3];
    float ss = v[0] * v[0] + v[1] * v[1] + v[2] * v[2] + v[3] * v[3];
    #pragma unroll
    for (int o = 16; o; o >>= 1) {
        s  += __shfl_xor_sync(0xffffffffu, s,  o);
        ss += __shfl_xor_sync(0xffffffffu, ss, o);
    }
    float mean = s * (1.f / 128.f);
    float var  = ss * (1.f / 128.f) - mean * mean;
    float inv  = rsqrtf(var + 1e-5f);
    #pragma unroll
    for (int q = 0; q < 4; q++) {
        float o_ = (v[q] - mean) * inv;
        g_hd[(size_t)r * HDIM + lane + 32 * q] = fmaxf(o_, 0.f);
    }
}

// ------ in-place row softmax * rowsum (no max-sub; logits bounded) -----------
__global__ __launch_bounds__(256)
void softmax_scale(float* __restrict__ out) {
    __shared__ __align__(16) float srow[N_GENES];
    __shared__ float sred[32];
    int r = blockIdx.x;
    float* row = out + (size_t)r * N_GENES;
    int tid = threadIdx.x;

    float s = 0.f;
    for (int i = tid; i < N_GENES / 4; i += 256) {
        float4 v = ((const float4*)row)[i];
        v.x = __expf(v.x); v.y = __expf(v.y);
        v.z = __expf(v.z); v.w = __expf(v.w);
        ((float4*)srow)[i] = v;
        s += (v.x + v.y) + (v.z + v.w);
    }
    #pragma unroll
    for (int o = 16; o; o >>= 1) s += __shfl_xor_sync(0xffffffffu, s, o);
    if ((tid & 31) == 0) sred[tid >> 5] = s;
    __syncthreads();
    if (tid < 32) {
        float t = (tid < 8) ? sred[tid] : 0.f;
        #pragma unroll
        for (int o = 4; o; o >>= 1) t += __shfl_xor_sync(0xffffffffu, t, o);
        if (tid == 0) sred[0] = t;
    }
    __syncthreads();
    float scale = g_rowsum[r] / sred[0];

    for (int i = tid; i < N_GENES / 4; i += 256) {
        float4 v = ((const float4*)srow)[i];
        v.x *= scale; v.y *= scale; v.z *= scale; v.w *= scale;
        ((float4*)row)[i] = v;
    }
}

// -----------------------------------------------------------------------------
extern "C" void kernel_launch(void* const* d_in, const int* in_sizes, int n_in,
                              void* d_out, int out_size) {
    const float* x       = (const float*)d_in[0];
    const int*   ei      = (const int*)d_in[1];
    const float* eps_z   = (const float*)d_in[3];
    const float* eps_gat = (const float*)d_in[4];
    const float* enc_W0  = (const float*)d_in[5];
    const float* enc_b0  = (const float*)d_in[6];
    const float* enc_W1  = (const float*)d_in[7];
    const float* enc_b1  = (const float*)d_in[8];
    const float* enc_Wm  = (const float*)d_in[9];
    const float* enc_bm  = (const float*)d_in[10];
    const float* enc_Wv  = (const float*)d_in[11];
    const float* enc_bv  = (const float*)d_in[12];
    const float* gm_Wl   = (const float*)d_in[13];
    const float* gm_bl   = (const float*)d_in[14];
    const float* gm_Wr   = (const float*)d_in[15];
    const float* gm_br   = (const float*)d_in[16];
    const float* gm_att  = (const float*)d_in[17];
    const float* gm_bias = (const float*)d_in[18];
    const float* gv_Wl   = (const float*)d_in[19];
    const float* gv_bl   = (const float*)d_in[20];
    const float* gv_Wr   = (const float*)d_in[21];
    const float* gv_br   = (const float*)d_in[22];
    const float* gv_att  = (const float*)d_in[23];
    const float* gv_bias = (const float*)d_in[24];
    const float* dec_W0  = (const float*)d_in[25];
    const float* dec_b0  = (const float*)d_in[26];
    const float* dec_Ws  = (const float*)d_in[27];
    const float* dec_bs  = (const float*)d_in[28];
    float* out = (float*)d_out;

    const int* e_src = ei;
    const int* e_dst = ei + N_EDGES;

    float *p_h0, *p_h1, *p_hd, *p_qmv, *p_biash;
    __half *p_bt0, *p_bt1, *p_btd, *p_bth;
    cudaGetSymbolAddress((void**)&p_h0, g_h0);
    cudaGetSymbolAddress((void**)&p_h1, g_h1);
    cudaGetSymbolAddress((void**)&p_hd, g_hd);
    cudaGetSymbolAddress((void**)&p_qmv, g_qmv);
    cudaGetSymbolAddress((void**)&p_biash, g_biash);
    cudaGetSymbolAddress((void**)&p_bt0, g_bt0);
    cudaGetSymbolAddress((void**)&p_bt1, g_bt1);
    cudaGetSymbolAddress((void**)&p_btd, g_btd);
    cudaGetSymbolAddress((void**)&p_bth, g_bth);

    cudaFuncSetAttribute(mma_gemm<true, true, true>,
                         cudaFuncAttributeMaxDynamicSharedMemorySize, SMEM_BYTES);
    cudaFuncSetAttribute(mma_gemm<false, true, false>,
                         cudaFuncAttributeMaxDynamicSharedMemorySize, SMEM_BYTES);
    cudaFuncSetAttribute(mma_gemm<false, false, false>,
                         cudaFuncAttributeMaxDynamicSharedMemorySize, SMEM_BYTES);

    const int MB = (N_NODES + 127) / 128;  // 235

    // weight prep (enc0 GEMM stays the 4th launch -> ncu slot)
    transpose_split<<<dim3(4, 63), dim3(32, 8)>>>(enc_W0, p_bt0, N_GENES, HDIM);
    transpose_split<<<dim3(4, 4),  dim3(32, 8)>>>(enc_W1, p_bt1, HDIM, HDIM);
    prep_heads<<<20, 256>>>(enc_Wm, enc_bm, enc_Wv, enc_bv);

    // encoder layer 0 (fused rowsum + log1p): h0 = relu(log1p(x) @ W0 + b0)
    mma_gemm<true, true, true><<<dim3(1, MB), 256, SMEM_BYTES>>>(
        x, p_bt0, enc_b0, p_h0, N_NODES, HDIM, N_GENES);
    // encoder layer 1
    mma_gemm<false, true, false><<<dim3(1, MB), 256, SMEM_BYTES>>>(
        p_h0, p_bt1, enc_b1, p_h1, N_NODES, HDIM, HDIM);
    // heads as GEMM: qmv[:, :20] = q_m, qmv[:, 20:] = pre-exp q_v
    mma_gemm<false, false, false><<<dim3(1, MB), 256, SMEM_BYTES>>>(
        p_h1, p_bth, p_biash, p_qmv, N_NODES, 40, HDIM);

    // GAT prep (merged z reparam + projections + accum zeroing), edge, finalize
    gat_pre<<<(N_NODES + 255) / 256, 256>>>(eps_z, gm_Wl, gm_bl, gm_Wr, gm_br,
                                            gv_Wl, gv_bl, gv_Wr, gv_br);
    transpose_split<<<dim3(63, 4), dim3(32, 8)>>>(dec_Ws, p_btd, HDIM, N_GENES);
    gat_edge<<<(N_EDGES + 255) / 256, 256>>>(e_src, e_dst, gm_att, gv_att);
    gat_fin<<<(N_NODES + 255) / 256, 256>>>(gm_bias, gv_bias, eps_gat);

    // decoder layer 0 + LN + relu
    dec0_ln<<<(N_NODES + 7) / 8, 256>>>(dec_W0, dec_b0);

    // decoder logits straight into d_out
    mma_gemm<false, false, false><<<dim3((N_GENES + 127) / 128, MB), 256, SMEM_BYTES>>>(
        p_hd, p_btd, dec_bs, out, N_NODES, N_GENES, HDIM);

    // in-place softmax * exp(library)
    softmax_scale<<<N_NODES, 256>>>(out);
}